// round 5
// baseline (speedup 1.0000x reference)
#include <cuda_runtime.h>
#include <cuda_fp16.h>

#define MAX_NODES 50000
#define MAX_EDGES 800000
#define DFEAT 64
#define DH2 (DFEAT / 2)     // 32 half2 per row
#define SCAN_B 1024
#define MAX_BLK ((MAX_NODES + SCAN_B - 1) / SCAN_B)

// ---- scratch (device globals; no allocation allowed) ----
__device__ int     g_deg[MAX_NODES];
__device__ int     g_cnt[MAX_NODES];
__device__ float   g_dinv[MAX_NODES];
__device__ int     g_rowptr[MAX_NODES + 1];
__device__ int     g_cursor[MAX_NODES];
__device__ int     g_bsum[MAX_BLK];
__device__ int     g_bpref[MAX_BLK];
__device__ int     g_col[MAX_EDGES];
__device__ float   g_w[MAX_EDGES];
__device__ __half2 g_xa[MAX_NODES * DH2];   // ping
__device__ __half2 g_xb[MAX_NODES * DH2];   // pong

__global__ void k_zero(int n) {
    int i = blockIdx.x * blockDim.x + threadIdx.x;
    if (i < n) { g_deg[i] = 0; g_cnt[i] = 0; }
}

__global__ void k_count(const int* __restrict__ src, const int* __restrict__ dst, int E) {
    int e = blockIdx.x * blockDim.x + threadIdx.x;
    if (e < E) {
        atomicAdd(&g_deg[src[e]], 1);
        atomicAdd(&g_cnt[dst[e]], 1);
    }
}

__global__ void k_dinv(int n) {
    int i = blockIdx.x * blockDim.x + threadIdx.x;
    if (i < n) {
        int d = g_deg[i];
        g_dinv[i] = (d > 0) ? rsqrtf((float)d) : 0.0f;
    }
}

// Convert feat (fp32) -> g_xa (half2). One thread per half2.
__global__ void k_half(const float* __restrict__ feat, int n2) {
    int i = blockIdx.x * blockDim.x + threadIdx.x;
    if (i < n2) {
        float2 f = reinterpret_cast<const float2*>(feat)[i];
        g_xa[i] = __float22half2_rn(f);
    }
}

// Phase 1: per-block inclusive scan of 1024 counts.
__global__ void k_scan1(int n) {
    __shared__ int s[SCAN_B];
    int t = threadIdx.x;
    int i = blockIdx.x * SCAN_B + t;
    int v = (i < n) ? g_cnt[i] : 0;
    s[t] = v;
    __syncthreads();
    for (int off = 1; off < SCAN_B; off <<= 1) {
        int u = (t >= off) ? s[t - off] : 0;
        __syncthreads();
        s[t] += u;
        __syncthreads();
    }
    if (i < n) g_rowptr[i] = s[t] - v;
    if (t == SCAN_B - 1) g_bsum[blockIdx.x] = s[t];
}

__global__ void k_scan2(int nb, int n) {
    if (threadIdx.x == 0) {
        int run = 0;
        for (int b = 0; b < nb; b++) {
            g_bpref[b] = run;
            run += g_bsum[b];
        }
        g_rowptr[n] = run;
    }
}

__global__ void k_scan3(int n) {
    int i = blockIdx.x * SCAN_B + threadIdx.x;
    if (i < n) {
        int r = g_rowptr[i] + g_bpref[blockIdx.x];
        g_rowptr[i] = r;
        g_cursor[i] = r;
    }
}

__global__ void k_fill(const int* __restrict__ src, const int* __restrict__ dst, int E) {
    int e = blockIdx.x * blockDim.x + threadIdx.x;
    if (e < E) {
        int d = dst[e];
        int s = src[e];
        int pos = atomicAdd(&g_cursor[d], 1);
        g_col[pos] = s;
        g_w[pos]   = g_dinv[s] * g_dinv[d];
    }
}

// One warp per output row. Lane owns features {2*lane, 2*lane+1} (one half2).
// Gathers x rows as half2 (one 128B line per edge per warp), accumulates fp32.
// Buffer selection happens INSIDE device code (device globals are not valid
// host-side kernel arguments): xin_sel/xout_sel: 1 = g_xa, 2 = g_xb, 0 = none.
__global__ void k_spmm(float* __restrict__ h, float theta, int init,
                       int xin_sel, int xout_sel, int n) {
    int warp = (blockIdx.x * blockDim.x + threadIdx.x) >> 5;
    int lane = threadIdx.x & 31;
    if (warp >= n) return;

    const __half2* __restrict__ x = (xin_sel == 1) ? g_xa : g_xb;
    __half2* xout = (xout_sel == 0) ? (__half2*)0 : ((xout_sel == 1) ? g_xa : g_xb);

    int beg = g_rowptr[warp];
    int end = g_rowptr[warp + 1];

    float a0 = 0.0f, a1 = 0.0f;
    int p = beg;
    for (; p + 3 < end; p += 4) {
        int   c0 = g_col[p],     c1 = g_col[p + 1];
        int   c2 = g_col[p + 2], c3 = g_col[p + 3];
        float w0 = g_w[p],       w1 = g_w[p + 1];
        float w2 = g_w[p + 2],   w3 = g_w[p + 3];
        __half2 v0 = x[c0 * DH2 + lane];
        __half2 v1 = x[c1 * DH2 + lane];
        __half2 v2 = x[c2 * DH2 + lane];
        __half2 v3 = x[c3 * DH2 + lane];
        float2 f0 = __half22float2(v0);
        float2 f1 = __half22float2(v1);
        float2 f2 = __half22float2(v2);
        float2 f3 = __half22float2(v3);
        a0 = fmaf(w0, f0.x, a0); a1 = fmaf(w0, f0.y, a1);
        a0 = fmaf(w1, f1.x, a0); a1 = fmaf(w1, f1.y, a1);
        a0 = fmaf(w2, f2.x, a0); a1 = fmaf(w2, f2.y, a1);
        a0 = fmaf(w3, f3.x, a0); a1 = fmaf(w3, f3.y, a1);
    }
    for (; p < end; p++) {
        int   c  = g_col[p];
        float wv = g_w[p];
        float2 f = __half22float2(x[c * DH2 + lane]);
        a0 = fmaf(wv, f.x, a0);
        a1 = fmaf(wv, f.y, a1);
    }

    if (xout) {
        xout[warp * DH2 + lane] = __float22half2_rn(make_float2(a0, a1));
    }
    float2* h2 = reinterpret_cast<float2*>(h) + warp * DH2 + lane;
    if (init) {
        *h2 = make_float2(theta * a0, theta * a1);
    } else {
        float2 cur = *h2;
        cur.x += theta * a0;
        cur.y += theta * a1;
        *h2 = cur;
    }
}

extern "C" void kernel_launch(void* const* d_in, const int* in_sizes, int n_in,
                              void* d_out, int out_size) {
    const float* feat = (const float*)d_in[0];
    const int*   src  = (const int*)d_in[1];
    const int*   dst  = (const int*)d_in[2];
    float*       h    = (float*)d_out;

    int n = in_sizes[0] / DFEAT;   // 50000
    int E = in_sizes[1];           // 800000

    int tb = 256;
    int gn = (n + tb - 1) / tb;
    int ge = (E + tb - 1) / tb;
    int nb = (n + SCAN_B - 1) / SCAN_B;
    int n2 = n * DH2;
    int g2 = (n2 + tb - 1) / tb;

    k_zero<<<gn, tb>>>(n);
    k_count<<<ge, tb>>>(src, dst, E);
    k_half<<<g2, tb>>>(feat, n2);
    k_dinv<<<gn, tb>>>(n);
    k_scan1<<<nb, SCAN_B>>>(n);
    k_scan2<<<1, 32>>>(nb, n);
    k_scan3<<<nb, SCAN_B>>>(n);
    k_fill<<<ge, tb>>>(src, dst, E);

    int gs = (n + 7) / 8;   // one warp per row, 8 warps/block
    // h  = 0.80 * (A @ f)      ; f in g_xa, x1 -> g_xb
    k_spmm<<<gs, tb>>>(h, 0.80f, 1, 1, 2, n);
    // h += 0.15 * (A @ x1)     ; x1 in g_xb, x2 -> g_xa
    k_spmm<<<gs, tb>>>(h, 0.15f, 0, 2, 1, n);
    // h += 0.05 * (A @ x2)     ; x2 in g_xa
    k_spmm<<<gs, tb>>>(h, 0.05f, 0, 1, 0, n);
}

// round 7
// speedup vs baseline: 1.0034x; 1.0034x over previous
#include <cuda_runtime.h>
#include <cuda_bf16.h>

#define MAX_NODES 50000
#define MAX_EDGES 800000
#define DFEAT 64
#define SCAN_B 1024
#define MAX_BLK ((MAX_NODES + SCAN_B - 1) / SCAN_B)

// ---- scratch (device globals; no allocation allowed) ----
__device__ int   g_deg[MAX_NODES];
__device__ int   g_cnt[MAX_NODES];
__device__ float g_dinv[MAX_NODES];
__device__ int   g_rowptr[MAX_NODES + 1];
__device__ int   g_cursor[MAX_NODES];
__device__ int   g_bsum[MAX_BLK];
__device__ float g_x1[MAX_NODES * DFEAT];
__device__ float g_x2[MAX_NODES * DFEAT];
__device__ int   g_col[MAX_EDGES];
__device__ float g_w[MAX_EDGES];

__global__ void k_zero(int n) {
    int i = blockIdx.x * blockDim.x + threadIdx.x;
    if (i < n) { g_deg[i] = 0; g_cnt[i] = 0; }
}

__global__ void k_count(const int* __restrict__ src, const int* __restrict__ dst, int E) {
    int e = blockIdx.x * blockDim.x + threadIdx.x;
    if (e < E) {
        atomicAdd(&g_deg[src[e]], 1);
        atomicAdd(&g_cnt[dst[e]], 1);
    }
}

// Fused: blocks [0, nb) run the per-block scan of g_cnt;
//        blocks [nb, 2nb) compute d^{-1/2}. Both depend only on k_count.
__global__ void k_prep(int n, int nb) {
    if ((int)blockIdx.x < nb) {
        // ---- scan phase 1: per-block inclusive scan of 1024 counts ----
        __shared__ int s[SCAN_B];
        int t = threadIdx.x;
        int i = blockIdx.x * SCAN_B + t;
        int v = (i < n) ? g_cnt[i] : 0;
        s[t] = v;
        __syncthreads();
        for (int off = 1; off < SCAN_B; off <<= 1) {
            int u = (t >= off) ? s[t - off] : 0;
            __syncthreads();
            s[t] += u;
            __syncthreads();
        }
        if (i < n) g_rowptr[i] = s[t] - v;           // exclusive within block
        if (t == SCAN_B - 1) g_bsum[blockIdx.x] = s[t];
    } else {
        // ---- dinv ----
        int i = (blockIdx.x - nb) * SCAN_B + threadIdx.x;
        if (i < n) {
            int d = g_deg[i];
            g_dinv[i] = (d > 0) ? rsqrtf((float)d) : 0.0f;
        }
    }
}

// Scan phases 2+3 fused: each block redundantly computes its own block-prefix
// from the <=49 block sums (trivial serial scan by thread 0), then adds it.
__global__ void k_scan3(int n, int nb) {
    __shared__ int pref;
    if (threadIdx.x == 0) {
        int run = 0;
        int b = (int)blockIdx.x;
        for (int j = 0; j < b; j++) run += g_bsum[j];
        pref = run;
        if (b == nb - 1) {
            int tot = run;
            for (int j = b; j < nb; j++) tot += g_bsum[j];
            g_rowptr[n] = tot;
        }
    }
    __syncthreads();
    int i = blockIdx.x * SCAN_B + threadIdx.x;
    if (i < n) {
        int r = g_rowptr[i] + pref;
        g_rowptr[i] = r;
        g_cursor[i] = r;
    }
}

__global__ void k_fill(const int* __restrict__ src, const int* __restrict__ dst, int E) {
    int e = blockIdx.x * blockDim.x + threadIdx.x;
    if (e < E) {
        int d = dst[e];
        int s = src[e];
        int pos = atomicAdd(&g_cursor[d], 1);
        g_col[pos] = s;
        g_w[pos]   = g_dinv[s] * g_dinv[d];
    }
}

// One warp per output row. Lane handles features {lane, lane+32}.
// xin_sel: 0 = feat param, 1 = g_x1, 2 = g_x2 ; xout_sel: 0 = none.
// Unroll 8 with front-batched col/w loads to maximize gather MLP.
__global__ void k_spmm(const float* __restrict__ feat, float* __restrict__ h,
                       float theta, int init, int xin_sel, int xout_sel, int n) {
    int warp = (blockIdx.x * blockDim.x + threadIdx.x) >> 5;
    int lane = threadIdx.x & 31;
    if (warp >= n) return;

    const float* __restrict__ x =
        (xin_sel == 0) ? feat : ((xin_sel == 1) ? (const float*)g_x1 : (const float*)g_x2);
    float* xout = (xout_sel == 0) ? (float*)0 : ((xout_sel == 1) ? g_x1 : g_x2);

    int beg = g_rowptr[warp];
    int end = g_rowptr[warp + 1];

    float a0 = 0.0f, a1 = 0.0f;
    int p = beg;
    for (; p + 7 < end; p += 8) {
        int c[8]; float wv[8];
#pragma unroll
        for (int j = 0; j < 8; j++) { c[j] = g_col[p + j]; wv[j] = g_w[p + j]; }
        float v0[8], v1[8];
#pragma unroll
        for (int j = 0; j < 8; j++) {
            const float* xr = x + (size_t)c[j] * DFEAT;
            v0[j] = xr[lane];
            v1[j] = xr[lane + 32];
        }
#pragma unroll
        for (int j = 0; j < 8; j++) {
            a0 = fmaf(wv[j], v0[j], a0);
            a1 = fmaf(wv[j], v1[j], a1);
        }
    }
    for (; p < end; p++) {
        int   c  = g_col[p];
        float wv = g_w[p];
        const float* xr = x + (size_t)c * DFEAT;
        a0 = fmaf(wv, xr[lane],      a0);
        a1 = fmaf(wv, xr[lane + 32], a1);
    }

    int o = warp * DFEAT + lane;
    if (xout) {
        xout[o]      = a0;
        xout[o + 32] = a1;
    }
    if (init) {
        h[o]      = theta * a0;
        h[o + 32] = theta * a1;
    } else {
        h[o]      += theta * a0;
        h[o + 32] += theta * a1;
    }
}

extern "C" void kernel_launch(void* const* d_in, const int* in_sizes, int n_in,
                              void* d_out, int out_size) {
    const float* feat = (const float*)d_in[0];
    const int*   src  = (const int*)d_in[1];
    const int*   dst  = (const int*)d_in[2];
    float*       h    = (float*)d_out;

    int n = in_sizes[0] / DFEAT;   // 50000
    int E = in_sizes[1];           // 800000

    int tb = 256;
    int gn = (n + tb - 1) / tb;
    int ge = (E + tb - 1) / tb;
    int nb = (n + SCAN_B - 1) / SCAN_B;

    k_zero<<<gn, tb>>>(n);
    k_count<<<ge, tb>>>(src, dst, E);
    k_prep<<<2 * nb, SCAN_B>>>(n, nb);
    k_scan3<<<nb, SCAN_B>>>(n, nb);
    k_fill<<<ge, tb>>>(src, dst, E);

    int gs = (n + 7) / 8;   // one warp per row, 8 warps/block
    // h  = 0.80 * (A @ f)      ; x1 -> g_x1
    k_spmm<<<gs, tb>>>(feat, h, 0.80f, 1, 0, 1, n);
    // h += 0.15 * (A @ x1)     ; x2 -> g_x2
    k_spmm<<<gs, tb>>>(feat, h, 0.15f, 0, 1, 2, n);
    // h += 0.05 * (A @ x2)
    k_spmm<<<gs, tb>>>(feat, h, 0.05f, 0, 2, 0, n);
}